// round 9
// baseline (speedup 1.0000x reference)
#include <cuda_runtime.h>
#include <cuda_fp16.h>

#define MAX_NODES (1 << 17)
__device__ float    g_lf[MAX_NODES];   // S[r] accumulator (pre-factored local field)
__device__ __half   g_xh[MAX_NODES];   // fp16 x for smem gather table
__device__ int      g_is32;            // 1 if edge_index is int32, 0 if int64
__device__ unsigned g_bar;             // software grid barrier counter

// Vectorized prep: zero g_lf, build fp16 table, reset barrier, detect width.
__global__ void prep_kernel(const float* __restrict__ x,
                            const void* __restrict__ ei, int n) {
    int i4 = blockIdx.x * blockDim.x + threadIdx.x;   // one float4 (4 nodes)
    int base = i4 * 4;
    if (base < n) {
        if (base + 3 < n) {
            float4 xv = *reinterpret_cast<const float4*>(x + base);
            *reinterpret_cast<float4*>(g_lf + base) =
                make_float4(0.f, 0.f, 0.f, 0.f);
            __half2 h01 = __floats2half2_rn(xv.x, xv.y);
            __half2 h23 = __floats2half2_rn(xv.z, xv.w);
            *reinterpret_cast<__half2*>(g_xh + base)     = h01;
            *reinterpret_cast<__half2*>(g_xh + base + 2) = h23;
        } else {
            for (int k = base; k < n; k++) {
                g_lf[k] = 0.0f;
                g_xh[k] = __float2half(x[k]);
            }
        }
    }
    if (blockIdx.x == 0) {
        if (threadIdx.x == 0) g_bar = 0;
        __shared__ int bad;
        if (threadIdx.x == 0) bad = 0;
        __syncthreads();
        if (threadIdx.x < 128) {
            const long long* p = (const long long*)ei;
            long long v = p[threadIdx.x];
            int is_bad = (v < 0 || v >= (long long)n) ? 1 : 0;
            unsigned m = __ballot_sync(0xFFFFFFFFu, is_bad);
            if ((threadIdx.x & 31) == 0 && m) atomicOr(&bad, 1);
        }
        __syncthreads();
        if (threadIdx.x == 0) g_is32 = bad;   // out-of-range int64 => really int32
    }
}

// Fused edge + MLP persistent kernel. Phase 1: scatter-add S[row] += x_h[col]
// (8 edges/thread/iter). Grid barrier. Phase 2: per-node 2-16-16 MLP.
__global__ void __launch_bounds__(512, 1)
fused_kernel(const float* __restrict__ x,
             const void* __restrict__ ei,
             const float* __restrict__ w1,
             const float* __restrict__ b1,
             const float* __restrict__ w2,
             const float* __restrict__ b2,
             float* __restrict__ out,
             long long E, int n) {
    extern __shared__ __half sx[];
    __shared__ float sw1[32], sb1[16], sw2[256], sb2[16];

    // --- stage fp16 x table + MLP weights into smem ---
    int nchunk = (n * 2 + 15) >> 4;
    const int4* src = reinterpret_cast<const int4*>(g_xh);
    int4* dst = reinterpret_cast<int4*>(sx);
    for (int i = threadIdx.x; i < nchunk; i += blockDim.x) dst[i] = src[i];
    {
        int tid = threadIdx.x;
        if (tid < 32) sw1[tid] = w1[tid];
        if (tid < 16) sb1[tid] = b1[tid];
        if (tid >= 16 && tid < 32) sb2[tid - 16] = b2[tid - 16];
        if (tid >= 32 && tid < 288) sw2[tid - 32] = w2[tid - 32];
    }
    __syncthreads();

    int is32 = g_is32;
    long long nvec = E >> 3;                 // 8 edges per thread-iter
    long long stride = (long long)gridDim.x * blockDim.x;

    // --- phase 1: edge scatter ---
    for (long long t = (long long)blockIdx.x * blockDim.x + threadIdx.x;
         t < nvec; t += stride) {
        long long base = t << 3;
        int r[8], c[8];
        if (is32) {
            const int* rows = (const int*)ei;
            const int* cols = rows + E;
            int4 ra = *reinterpret_cast<const int4*>(rows + base);
            int4 rb = *reinterpret_cast<const int4*>(rows + base + 4);
            int4 ca = *reinterpret_cast<const int4*>(cols + base);
            int4 cb = *reinterpret_cast<const int4*>(cols + base + 4);
            r[0]=ra.x; r[1]=ra.y; r[2]=ra.z; r[3]=ra.w;
            r[4]=rb.x; r[5]=rb.y; r[6]=rb.z; r[7]=rb.w;
            c[0]=ca.x; c[1]=ca.y; c[2]=ca.z; c[3]=ca.w;
            c[4]=cb.x; c[5]=cb.y; c[6]=cb.z; c[7]=cb.w;
        } else {
            const long long* rows = (const long long*)ei;
            const long long* cols = rows + E;
#pragma unroll
            for (int k = 0; k < 8; k += 2) {
                longlong2 rr = *reinterpret_cast<const longlong2*>(rows + base + k);
                longlong2 cc = *reinterpret_cast<const longlong2*>(cols + base + k);
                r[k] = (int)rr.x; r[k+1] = (int)rr.y;
                c[k] = (int)cc.x; c[k+1] = (int)cc.y;
            }
        }
        float v[8];
#pragma unroll
        for (int k = 0; k < 8; k++) v[k] = __half2float(sx[c[k]]);
#pragma unroll
        for (int k = 0; k < 8; k++) atomicAdd(&g_lf[r[k]], v[k]);
    }

    // tail (E not divisible by 8)
    if (blockIdx.x == 0 && threadIdx.x == 0) {
        for (long long e = nvec << 3; e < E; e++) {
            int rr, cc;
            if (is32) {
                const int* rows = (const int*)ei;
                rr = rows[e]; cc = rows[E + e];
            } else {
                const long long* rows = (const long long*)ei;
                rr = (int)rows[e]; cc = (int)rows[E + e];
            }
            atomicAdd(&g_lf[rr], __half2float(sx[cc]));
        }
    }

    // --- grid barrier ---
    __threadfence();
    __syncthreads();
    if (threadIdx.x == 0) {
        atomicAdd(&g_bar, 1u);
        while (*(volatile unsigned*)&g_bar < gridDim.x) { }
    }
    __syncthreads();
    __threadfence();

    // --- phase 2: MLP, grid-stride over nodes ---
    int gstride = gridDim.x * blockDim.x;
    for (int i = blockIdx.x * blockDim.x + threadIdx.x; i < n; i += gstride) {
        float xv = x[i];
        float lf = xv * g_lf[i];

        float h[16];
#pragma unroll
        for (int j = 0; j < 16; j++) {
            float v = fmaf(xv, sw1[2 * j], fmaf(lf, sw1[2 * j + 1], sb1[j]));
            h[j] = fmaxf(v, 0.0f);
        }
        float o[16];
#pragma unroll
        for (int k = 0; k < 16; k++) {
            float s = sb2[k];
#pragma unroll
            for (int j = 0; j < 16; j++) s = fmaf(h[j], sw2[k * 16 + j], s);
            o[k] = fmaxf(s, 0.0f);
        }
        float4* o4 = reinterpret_cast<float4*>(out + (size_t)i * 16);
        o4[0] = make_float4(o[0],  o[1],  o[2],  o[3]);
        o4[1] = make_float4(o[4],  o[5],  o[6],  o[7]);
        o4[2] = make_float4(o[8],  o[9],  o[10], o[11]);
        o4[3] = make_float4(o[12], o[13], o[14], o[15]);
    }
}

extern "C" void kernel_launch(void* const* d_in, const int* in_sizes, int n_in,
                              void* d_out, int out_size) {
    const float* x  = (const float*)d_in[0];
    const void*  ei = d_in[1];
    const float* w1 = (const float*)d_in[2];
    const float* b1 = (const float*)d_in[3];
    const float* w2 = (const float*)d_in[4];
    const float* b2 = (const float*)d_in[5];
    float*       out = (float*)d_out;

    int n = in_sizes[0];                        // x is [N, 1]
    long long E = (long long)in_sizes[1] / 2;   // edge_index is [2, E]

    size_t smem_bytes = ((size_t)n * 2 + 15) & ~(size_t)15;
    cudaFuncSetAttribute(fused_kernel,
                         cudaFuncAttributeMaxDynamicSharedMemorySize,
                         (int)smem_bytes);

    int prep_threads = (n + 3) / 4;
    prep_kernel<<<(prep_threads + 255) / 256, 256>>>(x, ei, n);
    fused_kernel<<<148, 512, smem_bytes>>>(x, ei, w1, b1, w2, b2, out, E, n);
}

// round 10
// speedup vs baseline: 2.4719x; 2.4719x over previous
#include <cuda_runtime.h>
#include <cuda_fp16.h>

#define MAX_NODES (1 << 17)
__device__ float  g_lf[MAX_NODES];   // S[r] accumulator (pre-factored local field)
__device__ __half g_xh[MAX_NODES];   // fp16 x for smem gather table
__device__ int    g_is32;            // 1 if edge_index is int32, 0 if int64

// Vectorized prep: zero g_lf, build fp16 table, detect index width.
__global__ void prep_kernel(const float* __restrict__ x,
                            const void* __restrict__ ei, int n) {
    int i4 = blockIdx.x * blockDim.x + threadIdx.x;   // one float4 (4 nodes)
    int base = i4 * 4;
    if (base < n) {
        if (base + 3 < n) {
            float4 xv = *reinterpret_cast<const float4*>(x + base);
            *reinterpret_cast<float4*>(g_lf + base) =
                make_float4(0.f, 0.f, 0.f, 0.f);
            *reinterpret_cast<__half2*>(g_xh + base)     = __floats2half2_rn(xv.x, xv.y);
            *reinterpret_cast<__half2*>(g_xh + base + 2) = __floats2half2_rn(xv.z, xv.w);
        } else {
            for (int k = base; k < n; k++) {
                g_lf[k] = 0.0f;
                g_xh[k] = __float2half(x[k]);
            }
        }
    }
    if (blockIdx.x == 0) {
        __shared__ int bad;
        if (threadIdx.x == 0) bad = 0;
        __syncthreads();
        if (threadIdx.x < 128) {
            const long long* p = (const long long*)ei;
            long long v = p[threadIdx.x];
            int is_bad = (v < 0 || v >= (long long)n) ? 1 : 0;
            unsigned m = __ballot_sync(0xFFFFFFFFu, is_bad);
            if ((threadIdx.x & 31) == 0 && m) atomicOr(&bad, 1);
        }
        __syncthreads();
        if (threadIdx.x == 0) g_is32 = bad;   // out-of-range int64 => really int32
    }
}

// Persistent edge kernel: stage fp16 x table in smem, stream edges,
// S[row] += (float)x_h[col]. 512 threads, 4 edges/thread (no spills).
__global__ void __launch_bounds__(512, 1)
edge_kernel(const void* __restrict__ ei, long long E, int n) {
    extern __shared__ __half sx[];

    int nchunk = (n * 2 + 15) >> 4;
    const int4* src = reinterpret_cast<const int4*>(g_xh);
    int4* dst = reinterpret_cast<int4*>(sx);
    for (int i = threadIdx.x; i < nchunk; i += blockDim.x) dst[i] = src[i];
    __syncthreads();

    int is32 = g_is32;
    long long nvec = E >> 2;
    long long stride = (long long)gridDim.x * blockDim.x;

    for (long long t = (long long)blockIdx.x * blockDim.x + threadIdx.x;
         t < nvec; t += stride) {
        long long base = t << 2;
        int r[4], c[4];
        if (is32) {
            const int* rows = (const int*)ei;
            const int* cols = rows + E;
            int4 ra = *reinterpret_cast<const int4*>(rows + base);
            int4 ca = *reinterpret_cast<const int4*>(cols + base);
            r[0] = ra.x; r[1] = ra.y; r[2] = ra.z; r[3] = ra.w;
            c[0] = ca.x; c[1] = ca.y; c[2] = ca.z; c[3] = ca.w;
        } else {
            const long long* rows = (const long long*)ei;
            const long long* cols = rows + E;
            longlong2 ra = *reinterpret_cast<const longlong2*>(rows + base);
            longlong2 rb = *reinterpret_cast<const longlong2*>(rows + base + 2);
            longlong2 ca = *reinterpret_cast<const longlong2*>(cols + base);
            longlong2 cb = *reinterpret_cast<const longlong2*>(cols + base + 2);
            r[0] = (int)ra.x; r[1] = (int)ra.y; r[2] = (int)rb.x; r[3] = (int)rb.y;
            c[0] = (int)ca.x; c[1] = (int)ca.y; c[2] = (int)cb.x; c[3] = (int)cb.y;
        }
        float v[4];
#pragma unroll
        for (int k = 0; k < 4; k++) v[k] = __half2float(sx[c[k]]);
#pragma unroll
        for (int k = 0; k < 4; k++) atomicAdd(&g_lf[r[k]], v[k]);
    }

    if (blockIdx.x == 0 && threadIdx.x == 0) {
        for (long long e = nvec << 2; e < E; e++) {
            int rr, cc;
            if (is32) {
                const int* rows = (const int*)ei;
                rr = rows[e]; cc = rows[E + e];
            } else {
                const long long* rows = (const long long*)ei;
                rr = (int)rows[e]; cc = (int)rows[E + e];
            }
            atomicAdd(&g_lf[rr], __half2float(sx[cc]));
        }
    }
}

// Two nodes per thread (i, i+blockDim): amortizes w2 LDS over both nodes,
// and reads w2 as float4 (4x fewer LDS). All accesses stay coalesced.
// lf = x[i] * S[i] (factored multiply applied here).
__global__ void mlp_kernel(const float* __restrict__ x,
                           const float* __restrict__ w1,
                           const float* __restrict__ b1,
                           const float* __restrict__ w2,
                           const float* __restrict__ b2,
                           float* __restrict__ out,
                           int n) {
    __shared__ float sw1[32];
    __shared__ float sb1[16];
    __shared__ __align__(16) float sw2[256];
    __shared__ float sb2[16];

    int tid = threadIdx.x;
    if (tid < 32) sw1[tid] = w1[tid];
    if (tid < 16) sb1[tid] = b1[tid];
    if (tid >= 16 && tid < 32) sb2[tid - 16] = b2[tid - 16];
    for (int i = tid; i < 256; i += blockDim.x) sw2[i] = w2[i];
    __syncthreads();

    int ia = blockIdx.x * (blockDim.x * 2) + tid;
    int ib = ia + blockDim.x;
    bool va = (ia < n), vb = (ib < n);
    if (!va) return;

    float xa = x[ia];
    float lfa = xa * g_lf[ia];
    float xb = 0.f, lfb = 0.f;
    if (vb) { xb = x[ib]; lfb = xb * g_lf[ib]; }

    float ha[16], hb[16];
#pragma unroll
    for (int j = 0; j < 16; j++) {
        float w0 = sw1[2 * j], w1v = sw1[2 * j + 1], bj = sb1[j];
        ha[j] = fmaxf(fmaf(xa, w0, fmaf(lfa, w1v, bj)), 0.0f);
        hb[j] = fmaxf(fmaf(xb, w0, fmaf(lfb, w1v, bj)), 0.0f);
    }

    const float4* sw24 = reinterpret_cast<const float4*>(sw2);
    float oa[16], ob[16];
#pragma unroll
    for (int k = 0; k < 16; k++) {
        float sa = sb2[k], sb = sa;
#pragma unroll
        for (int jj = 0; jj < 4; jj++) {
            float4 w = sw24[k * 4 + jj];
            int j = jj * 4;
            sa = fmaf(ha[j],     w.x, sa);  sb = fmaf(hb[j],     w.x, sb);
            sa = fmaf(ha[j + 1], w.y, sa);  sb = fmaf(hb[j + 1], w.y, sb);
            sa = fmaf(ha[j + 2], w.z, sa);  sb = fmaf(hb[j + 2], w.z, sb);
            sa = fmaf(ha[j + 3], w.w, sa);  sb = fmaf(hb[j + 3], w.w, sb);
        }
        oa[k] = fmaxf(sa, 0.0f);
        ob[k] = fmaxf(sb, 0.0f);
    }

    float4* o4a = reinterpret_cast<float4*>(out + (size_t)ia * 16);
    o4a[0] = make_float4(oa[0],  oa[1],  oa[2],  oa[3]);
    o4a[1] = make_float4(oa[4],  oa[5],  oa[6],  oa[7]);
    o4a[2] = make_float4(oa[8],  oa[9],  oa[10], oa[11]);
    o4a[3] = make_float4(oa[12], oa[13], oa[14], oa[15]);
    if (vb) {
        float4* o4b = reinterpret_cast<float4*>(out + (size_t)ib * 16);
        o4b[0] = make_float4(ob[0],  ob[1],  ob[2],  ob[3]);
        o4b[1] = make_float4(ob[4],  ob[5],  ob[6],  ob[7]);
        o4b[2] = make_float4(ob[8],  ob[9],  ob[10], ob[11]);
        o4b[3] = make_float4(ob[12], ob[13], ob[14], ob[15]);
    }
}

extern "C" void kernel_launch(void* const* d_in, const int* in_sizes, int n_in,
                              void* d_out, int out_size) {
    const float* x  = (const float*)d_in[0];
    const void*  ei = d_in[1];
    const float* w1 = (const float*)d_in[2];
    const float* b1 = (const float*)d_in[3];
    const float* w2 = (const float*)d_in[4];
    const float* b2 = (const float*)d_in[5];
    float*       out = (float*)d_out;

    int n = in_sizes[0];                        // x is [N, 1]
    long long E = (long long)in_sizes[1] / 2;   // edge_index is [2, E]

    size_t smem_bytes = ((size_t)n * 2 + 15) & ~(size_t)15;
    cudaFuncSetAttribute(edge_kernel,
                         cudaFuncAttributeMaxDynamicSharedMemorySize,
                         (int)smem_bytes);

    int prep_threads = (n + 3) / 4;
    prep_kernel<<<(prep_threads + 255) / 256, 256>>>(x, ei, n);
    edge_kernel<<<148, 512, smem_bytes>>>(ei, E, n);

    int mlp_tpb = 256;   // 512 nodes per block
    int mlp_blocks = (n + mlp_tpb * 2 - 1) / (mlp_tpb * 2);
    mlp_kernel<<<mlp_blocks, mlp_tpb>>>(x, w1, b1, w2, b2, out, n);
}